// round 5
// baseline (speedup 1.0000x reference)
#include <cuda_runtime.h>

// GrassmannNN: SITE=8, DIM=16, D=32, B=8192.
//
// Reduction: all parity merges/unmerges cancel; each body layer reduces to
//   out_s = tanh( sign * u_src @ M[layer][bit][s] )   (16x16 matvec)
// where M depends only on (layer, bit). The whole net depends only on the
// 8-bit pattern data[b,:], so we compute 256 pattern outputs and gather.

#define NPAT 256

__device__ float g_M[7 * 2 * 2 * 256];          // [l][bit][s][i][k], sign folded
__device__ float g_h[32];                       // head vectors per bit
__device__ __align__(16) float g_T[NPAT * 64];  // pattern output table (B,2,32) layout

// ---------------------------------------------------------------------------
// Kernel A: precompute layer matrices M and head vectors.
// M[l][bit][s][i][k] = sum_j emb[l+1][bit][j] * body_w[l][ig][jg][kg]
//   ig = 16*s1 + i  (s1 = bit ? 1-s : s),  jg = 16*bit + j,  kg = 16*s + k
// sign (-1 iff bit==1 && s==0) folded into M.
// ---------------------------------------------------------------------------
__global__ void precompute_kernel(const float* __restrict__ emb,
                                  const float* __restrict__ head_w,
                                  const float* __restrict__ body_w) {
    int tid = blockIdx.x * blockDim.x + threadIdx.x;
    if (tid < 7168) {
        int k   = tid & 15;
        int i   = (tid >> 4) & 15;
        int s   = (tid >> 8) & 1;
        int bit = (tid >> 9) & 1;
        int l   = tid >> 10;                       // 0..6  (site l+1)
        int s1  = bit ? (1 - s) : s;
        int ig  = s1 * 16 + i;
        int kg  = s * 16 + k;
        const float* e = emb + ((l + 1) * 2 + bit) * 16;
        const float* g = body_w + ((size_t)((l * 32 + ig) * 32 + bit * 16)) * 32 + kg;
        float acc = 0.f;
#pragma unroll
        for (int j = 0; j < 16; ++j)
            acc = fmaf(e[j], g[(size_t)j * 32], acc);
        if (bit == 1 && s == 0) acc = -acc;
        g_M[tid] = acc;
    } else if (tid < 7168 + 32) {
        int t = tid - 7168;
        int j = t & 15;
        int bit = t >> 4;
        const float* e = emb + bit * 16;           // embedding[0][bit]
        float acc = 0.f;
#pragma unroll
        for (int k = 0; k < 16; ++k)
            acc = fmaf(e[k], head_w[(bit * 16 + k) * 32 + bit * 16 + j], acc);
        g_h[t] = tanhf(acc);
    }
}

// ---------------------------------------------------------------------------
// Kernel B: forward all 256 patterns. One warp per pattern; lane (s,k) holds
// state u[s][k]; 16x16 matvec via warp shuffles.
// ---------------------------------------------------------------------------
__global__ void pattern_kernel() {
    int warp = (blockIdx.x * blockDim.x + threadIdx.x) >> 5;
    int lane = threadIdx.x & 31;
    if (warp >= NPAT) return;
    int p = warp;
    int s = lane >> 4;
    int k = lane & 15;

    int bit0 = p & 1;
    float u = (s == bit0) ? g_h[bit0 * 16 + k] : 0.f;

#pragma unroll
    for (int l = 0; l < 7; ++l) {
        int bit = (p >> (l + 1)) & 1;
        const float* Mp = g_M + (((l * 2 + bit) * 2 + s) * 256) + k;
        int src = (bit ? (1 - s) : s) << 4;
        float acc = 0.f;
#pragma unroll
        for (int i = 0; i < 16; ++i) {
            float v = __shfl_sync(0xffffffffu, u, src + i);
            acc = fmaf(v, Mp[i * 16], acc);
        }
        u = tanhf(acc);
    }

    // out[p][s][:] : sector s lives in half s; other half exactly zero.
    float* o = g_T + p * 64;
    o[48 * s + k] = u;               // value: offset s*32 + s*16 + k
    o[16 + 16 * s + k] = 0.f;        // zero:  offset s*32 + (1-s)*16 + k
}

// ---------------------------------------------------------------------------
// Kernel C: gather — each row copies its 64-float pattern output.
// ---------------------------------------------------------------------------
__global__ void gather_kernel(const int* __restrict__ data,
                              float4* __restrict__ out) {
    int tid = blockIdx.x * blockDim.x + threadIdx.x;   // 8192*16 = 131072
    int row = tid >> 4;
    int q   = tid & 15;
    const int4* d4 = reinterpret_cast<const int4*>(data + (size_t)row * 8);
    int4 a = __ldg(d4);
    int4 b = __ldg(d4 + 1);
    int p = a.x | (a.y << 1) | (a.z << 2) | (a.w << 3)
          | (b.x << 4) | (b.y << 5) | (b.z << 6) | (b.w << 7);
    out[tid] = reinterpret_cast<const float4*>(g_T)[p * 16 + q];
}

extern "C" void kernel_launch(void* const* d_in, const int* in_sizes, int n_in,
                              void* d_out, int out_size) {
    const int*   data      = (const int*)d_in[0];    // (8192, 8) int32
    const float* embedding = (const float*)d_in[1];  // (8, 2, 16)
    const float* head_w    = (const float*)d_in[2];  // (32, 32)
    const float* body_w    = (const float*)d_in[3];  // (7, 32, 32, 32)
    float* out = (float*)d_out;                      // (8192, 2, 32)

    precompute_kernel<<<29, 256>>>(embedding, head_w, body_w);
    pattern_kernel<<<32, 256>>>();
    gather_kernel<<<512, 256>>>(data, (float4*)out);
}